// round 10
// baseline (speedup 1.0000x reference)
#include <cuda_runtime.h>
#include <cuda_bf16.h>

#define T_LEN   4000
#define THREADS 256
#define NSEG    4       // 4 segments x 1024 = 4096 >= 4000
#define NROW    2       // rows per block (ILP pair)

__device__ __forceinline__ float fsqrt_approx(float u) {
    float r; asm("sqrt.approx.f32 %0, %1;" : "=f"(r) : "f"(u)); return r;
}
__device__ __forceinline__ float flg2(float u) {
    float r; asm("lg2.approx.f32 %0, %1;" : "=f"(r) : "f"(u)); return r;
}
__device__ __forceinline__ float fex2(float u) {
    float r; asm("ex2.approx.f32 %0, %1;" : "=f"(r) : "f"(u)); return r;
}

__global__ __launch_bounds__(THREADS, 6)
void pcen_kernel(const float* __restrict__ x, float* __restrict__ out)
{
    __shared__ float sT[NROW][32];   // per-row 128-element chunk totals

    const float a      = 0.975f;     // 1 - S
    const float S_     = 0.025f;
    const float NALPHA = -0.98f;
    const float DELTA  = 2.0f;
    const float EPSf   = 1e-6f;
    const float DR     = 1.41421356237309515f;  // sqrt(2)

    // compile-time powers of a
    const float a2 = a*a, a4 = a2*a2, a8 = a4*a4, a16 = a8*a8,
                a32 = a16*a16, a64 = a32*a32, a128 = a64*a64,
                a256 = a128*a128, a512 = a256*a256,
                a1024 = a512*a512, a2048 = a1024*a1024;

    const int tid  = threadIdx.x;
    const int lane = tid & 31, warp = tid >> 5;   // 8 warps
    const float* __restrict__ xr   = x   + (size_t)blockIdx.x * (NROW * T_LEN);
    float* __restrict__       orow = out + (size_t)blockIdx.x * (NROW * T_LEN);

    // a^(4*lane), exact bit product
    float A4L = 1.0f;
    if (lane & 1)  A4L *= a4;
    if (lane & 2)  A4L *= a8;
    if (lane & 4)  A4L *= a16;
    if (lane & 8)  A4L *= a32;
    if (lane & 16) A4L *= a64;

    // ---- pass 1 (streaming, 2 rows interleaved): fold + warp scan ----
    // b[0] = x[0] (per-row init), b[t] = S*x[t] otherwise
    float P0[NSEG], P1[NSEG];
    #pragma unroll
    for (int j = 0; j < NSEG; j++) {
        int i = j * 1024 + tid * 4;
        float4 t0 = make_float4(0.f,0.f,0.f,0.f), t1 = t0;
        if (i < T_LEN) {
            t0 = *reinterpret_cast<const float4*>(xr + i);
            t1 = *reinterpret_cast<const float4*>(xr + T_LEN + i);
        }
        float h0 = (j == 0 && tid == 0) ? t0.x : S_ * t0.x;
        float h1 = (j == 0 && tid == 0) ? t1.x : S_ * t1.x;
        h0 = fmaf(a, h0, S_ * t0.y);  h1 = fmaf(a, h1, S_ * t1.y);
        h0 = fmaf(a, h0, S_ * t0.z);  h1 = fmaf(a, h1, S_ * t1.z);
        h0 = fmaf(a, h0, S_ * t0.w);  h1 = fmaf(a, h1, S_ * t1.w);

        float y0 = h0, y1 = h1, p0, p1;
        p0 = __shfl_up_sync(0xFFFFFFFFu, y0, 1);  p1 = __shfl_up_sync(0xFFFFFFFFu, y1, 1);
        if (lane >= 1)  { y0 = fmaf(a4,  p0, y0); y1 = fmaf(a4,  p1, y1); }
        p0 = __shfl_up_sync(0xFFFFFFFFu, y0, 2);  p1 = __shfl_up_sync(0xFFFFFFFFu, y1, 2);
        if (lane >= 2)  { y0 = fmaf(a8,  p0, y0); y1 = fmaf(a8,  p1, y1); }
        p0 = __shfl_up_sync(0xFFFFFFFFu, y0, 4);  p1 = __shfl_up_sync(0xFFFFFFFFu, y1, 4);
        if (lane >= 4)  { y0 = fmaf(a16, p0, y0); y1 = fmaf(a16, p1, y1); }
        p0 = __shfl_up_sync(0xFFFFFFFFu, y0, 8);  p1 = __shfl_up_sync(0xFFFFFFFFu, y1, 8);
        if (lane >= 8)  { y0 = fmaf(a32, p0, y0); y1 = fmaf(a32, p1, y1); }
        p0 = __shfl_up_sync(0xFFFFFFFFu, y0, 16); p1 = __shfl_up_sync(0xFFFFFFFFu, y1, 16);
        if (lane >= 16) { y0 = fmaf(a64, p0, y0); y1 = fmaf(a64, p1, y1); }

        P0[j] = y0;  P1[j] = y1;
        if (lane == 31) { sT[0][j * 8 + warp] = y0; sT[1][j * 8 + warp] = y1; }
    }
    __syncthreads();

    // ---- middle scan over 32 chunks per row, redundantly in every warp ----
    float y0 = sT[0][lane], y1 = sT[1][lane], p0, p1;
    p0 = __shfl_up_sync(0xFFFFFFFFu, y0, 1);  p1 = __shfl_up_sync(0xFFFFFFFFu, y1, 1);
    if (lane >= 1)  { y0 = fmaf(a128,  p0, y0); y1 = fmaf(a128,  p1, y1); }
    p0 = __shfl_up_sync(0xFFFFFFFFu, y0, 2);  p1 = __shfl_up_sync(0xFFFFFFFFu, y1, 2);
    if (lane >= 2)  { y0 = fmaf(a256,  p0, y0); y1 = fmaf(a256,  p1, y1); }
    p0 = __shfl_up_sync(0xFFFFFFFFu, y0, 4);  p1 = __shfl_up_sync(0xFFFFFFFFu, y1, 4);
    if (lane >= 4)  { y0 = fmaf(a512,  p0, y0); y1 = fmaf(a512,  p1, y1); }
    p0 = __shfl_up_sync(0xFFFFFFFFu, y0, 8);  p1 = __shfl_up_sync(0xFFFFFFFFu, y1, 8);
    if (lane >= 8)  { y0 = fmaf(a1024, p0, y0); y1 = fmaf(a1024, p1, y1); }
    p0 = __shfl_up_sync(0xFFFFFFFFu, y0, 16); p1 = __shfl_up_sync(0xFFFFFFFFu, y1, 16);
    if (lane >= 16) { y0 = fmaf(a2048, p0, y0); y1 = fmaf(a2048, p1, y1); }
    float e0 = __shfl_up_sync(0xFFFFFFFFu, y0, 1);
    float e1 = __shfl_up_sync(0xFFFFFFFFu, y1, 1);
    if (lane == 0) { e0 = 0.f; e1 = 0.f; }   // exclusive carry of chunk 'lane'

    // ---- pass 2: re-read x (L1 hit), seeded recurrences + PCEN, store ----
    #pragma unroll
    for (int j = 0; j < NSEG; j++) {
        float Cw0 = __shfl_sync(0xFFFFFFFFu, e0, j * 8 + warp);
        float Cw1 = __shfl_sync(0xFFFFFFFFu, e1, j * 8 + warp);
        float E0  = __shfl_up_sync(0xFFFFFFFFu, P0[j], 1);
        float E1  = __shfl_up_sync(0xFFFFFFFFu, P1[j], 1);
        if (lane == 0) { E0 = 0.f; E1 = 0.f; }
        float sm0 = fmaf(A4L, Cw0, E0);
        float sm1 = fmaf(A4L, Cw1, E1);

        int i = j * 1024 + tid * 4;
        if (i < T_LEN) {
            float4 t0 = *reinterpret_cast<const float4*>(xr + i);          // L1-resident
            float4 t1 = *reinterpret_cast<const float4*>(xr + T_LEN + i);  // L1-resident

            float b00 = (j == 0 && tid == 0) ? t0.x : S_ * t0.x;
            float b10 = (j == 0 && tid == 0) ? t1.x : S_ * t1.x;
            sm0 = fmaf(a, sm0, b00);
            sm1 = fmaf(a, sm1, b10);
            float r00 = fsqrt_approx(fmaf(t0.x, fex2(NALPHA * flg2(sm0 + EPSf)), DELTA)) - DR;
            float r10 = fsqrt_approx(fmaf(t1.x, fex2(NALPHA * flg2(sm1 + EPSf)), DELTA)) - DR;

            sm0 = fmaf(a, sm0, S_ * t0.y);  sm1 = fmaf(a, sm1, S_ * t1.y);
            float r01 = fsqrt_approx(fmaf(t0.y, fex2(NALPHA * flg2(sm0 + EPSf)), DELTA)) - DR;
            float r11 = fsqrt_approx(fmaf(t1.y, fex2(NALPHA * flg2(sm1 + EPSf)), DELTA)) - DR;

            sm0 = fmaf(a, sm0, S_ * t0.z);  sm1 = fmaf(a, sm1, S_ * t1.z);
            float r02 = fsqrt_approx(fmaf(t0.z, fex2(NALPHA * flg2(sm0 + EPSf)), DELTA)) - DR;
            float r12 = fsqrt_approx(fmaf(t1.z, fex2(NALPHA * flg2(sm1 + EPSf)), DELTA)) - DR;

            sm0 = fmaf(a, sm0, S_ * t0.w);  sm1 = fmaf(a, sm1, S_ * t1.w);
            float r03 = fsqrt_approx(fmaf(t0.w, fex2(NALPHA * flg2(sm0 + EPSf)), DELTA)) - DR;
            float r13 = fsqrt_approx(fmaf(t1.w, fex2(NALPHA * flg2(sm1 + EPSf)), DELTA)) - DR;

            *reinterpret_cast<float4*>(orow + i)         = make_float4(r00, r01, r02, r03);
            *reinterpret_cast<float4*>(orow + T_LEN + i) = make_float4(r10, r11, r12, r13);
        }
    }
}

extern "C" void kernel_launch(void* const* d_in, const int* in_sizes, int n_in,
                              void* d_out, int out_size)
{
    const float* x = (const float*)d_in[0];
    float* out = (float*)d_out;
    int rows = in_sizes[0] / T_LEN;   // 8192
    pcen_kernel<<<rows / NROW, THREADS>>>(x, out);
}